// round 1
// baseline (speedup 1.0000x reference)
#include <cuda_runtime.h>
#include <math.h>

// Problem constants
#define B_   32
#define SEQ_ 577
#define H_   16
#define HD_  88
#define D_   1408
#define IDX_ 24
#define M_   (B_ * SEQ_)   // 18464

// Scratch (device globals: no allocation allowed in kernel_launch)
__device__ float g_Q[(size_t)M_ * D_];
__device__ float g_K[(size_t)M_ * D_];
__device__ float g_V[(size_t)M_ * D_];
__device__ float g_C[(size_t)M_ * D_];
__device__ float g_cos[SEQ_ * 44];
__device__ float g_sin[SEQ_ * 44];

// ---------------------------------------------------------------------------
// GEMM: C[M][1408] = A[M][1408] @ W[1408][1408]^T + bias   (fp32 SIMT)
// 128x128x8 tiles, 256 threads, 8x8 microtile per thread.
// ---------------------------------------------------------------------------
constexpr int BM = 128, BN = 128, BK = 8;

__global__ __launch_bounds__(256) void gemm_bias_kernel(
    const float* __restrict__ A, const float* __restrict__ W,
    const float* __restrict__ bias, float* __restrict__ C, int M)
{
    __shared__ __align__(16) float As[BK][BM + 4];   // stride 132: conflict-free store
    __shared__ __align__(16) float Bs[BK][BN + 4];

    const int bm = blockIdx.y * BM;
    const int bn = blockIdx.x * BN;
    const int t  = threadIdx.x;       // 0..255
    const int tm = t >> 4;            // 0..15
    const int tn = t & 15;            // 0..15

    float acc[8][8];
#pragma unroll
    for (int i = 0; i < 8; i++)
#pragma unroll
        for (int j = 0; j < 8; j++) acc[i][j] = 0.f;

    for (int k0 = 0; k0 < D_; k0 += BK) {
#pragma unroll
        for (int i = 0; i < 4; i++) {
            int idx = t + 256 * i;       // 0..1023
            int kk  = idx & 7;
            int mm  = idx >> 3;
            int gm  = bm + mm;
            As[kk][mm] = (gm < M) ? A[(size_t)gm * D_ + k0 + kk] : 0.f;
            Bs[kk][mm] = W[(size_t)(bn + mm) * D_ + k0 + kk];   // N = 1408 exact
        }
        __syncthreads();

#pragma unroll
        for (int kk = 0; kk < BK; kk++) {
            float4 a0 = *(const float4*)&As[kk][tm * 8];
            float4 a1 = *(const float4*)&As[kk][tm * 8 + 4];
            float4 b0 = *(const float4*)&Bs[kk][tn * 8];
            float4 b1 = *(const float4*)&Bs[kk][tn * 8 + 4];
            float av[8] = {a0.x, a0.y, a0.z, a0.w, a1.x, a1.y, a1.z, a1.w};
            float bv[8] = {b0.x, b0.y, b0.z, b0.w, b1.x, b1.y, b1.z, b1.w};
#pragma unroll
            for (int i = 0; i < 8; i++)
#pragma unroll
                for (int j = 0; j < 8; j++) acc[i][j] += av[i] * bv[j];
        }
        __syncthreads();
    }

    float bcol[8];
#pragma unroll
    for (int j = 0; j < 8; j++) bcol[j] = bias[bn + tn * 8 + j];

#pragma unroll
    for (int i = 0; i < 8; i++) {
        int gm = bm + tm * 8 + i;
        if (gm >= M) continue;
#pragma unroll
        for (int j = 0; j < 8; j += 4) {
            float4 v;
            v.x = acc[i][j]     + bcol[j];
            v.y = acc[i][j + 1] + bcol[j + 1];
            v.z = acc[i][j + 2] + bcol[j + 2];
            v.w = acc[i][j + 3] + bcol[j + 3];
            *(float4*)&C[(size_t)gm * D_ + bn + tn * 8 + j] = v;
        }
    }
}

// ---------------------------------------------------------------------------
// Rope tables: HF llama4 vision rope. freq_dim=44, rope_freq[i]=theta^{-2i/44},
// i=0..21; freqs[s] = [(fx+1)*rf[0..21], (fy+1)*rf[0..21]]; CLS (s=576) -> 0.
// ---------------------------------------------------------------------------
__global__ void rope_init_kernel()
{
    int idx = blockIdx.x * blockDim.x + threadIdx.x;
    if (idx >= SEQ_ * 44) return;
    int s = idx / 44, j = idx % 44;
    double f = 0.0;
    if (s != SEQ_ - 1) {
        int fx = s % IDX_, fy = s / IDX_;
        int i = (j < 22) ? j : j - 22;
        double rf = exp((-2.0 * (double)i / 44.0) * log(10000.0));
        double coord = (j < 22) ? (double)(fx + 1) : (double)(fy + 1);
        f = coord * rf;
    }
    g_cos[idx] = (float)cos(f);
    g_sin[idx] = (float)sin(f);
}

__global__ void rope_apply_kernel()
{
    int idx = blockIdx.x * blockDim.x + threadIdx.x;
    const int total = B_ * SEQ_ * H_ * 44;
    if (idx >= total) return;
    int j    = idx % 44;
    int rest = idx / 44;                 // (b*SEQ + s)*H + h
    int s    = (rest / H_) % SEQ_;
    size_t base = (size_t)rest * HD_ + 2 * j;
    float c  = g_cos[s * 44 + j];
    float sn = g_sin[s * 44 + j];

    float a = g_Q[base], b = g_Q[base + 1];
    g_Q[base]     = a * c - b * sn;
    g_Q[base + 1] = a * sn + b * c;
    a = g_K[base]; b = g_K[base + 1];
    g_K[base]     = a * c - b * sn;
    g_K[base + 1] = a * sn + b * c;
}

// ---------------------------------------------------------------------------
// Flash attention (fp32). Block = (b, h, 32 queries). 256 threads, 8 warps.
// Q row cached in registers (q = lane). K read as warp-uniform float4
// broadcasts. V transposed in shared so PV phase is float4-broadcast-fed.
// ---------------------------------------------------------------------------
__global__ __launch_bounds__(256) void attn_kernel(
    const float* __restrict__ Q, const float* __restrict__ K,
    const float* __restrict__ V, float* __restrict__ O)
{
    const int qt = blockIdx.x, h = blockIdx.y, b = blockIdx.z;
    const int q0 = qt * 32;

    __shared__ __align__(16) float Qs[32][89];   // staging only
    __shared__ __align__(16) float Ks[32][92];   // float4-aligned rows
    __shared__ __align__(16) float VsT[HD_][36]; // transposed V, float4-aligned
    __shared__ __align__(16) float Ps[32][36];
    __shared__ float m_sh[32], l_sh[32], corr_sh[32];

    const int t    = threadIdx.x;
    const int lane = t & 31;
    const int warp = t >> 5;
    const int dbase = warp * 11;     // 8 warps * 11 dims = 88

    for (int idx = t; idx < 32 * HD_; idx += 256) {
        int qq = idx / HD_, d = idx % HD_;
        int s = q0 + qq;
        Qs[qq][d] = (s < SEQ_) ? Q[(((size_t)b * SEQ_ + s) * H_ + h) * HD_ + d] : 0.f;
    }
    if (t < 32) { m_sh[t] = -1e30f; l_sh[t] = 0.f; }
    __syncthreads();

    float qreg[HD_];
#pragma unroll
    for (int d = 0; d < HD_; d++) qreg[d] = Qs[lane][d];

    float acc[11];
#pragma unroll
    for (int i = 0; i < 11; i++) acc[i] = 0.f;

    const float scale = 0.10660035817780521f;   // 88^-0.5

    for (int k0 = 0; k0 < SEQ_; k0 += 32) {
        // load K tile + transposed V tile
        for (int idx = t; idx < 32 * HD_; idx += 256) {
            int kk = idx / HD_, d = idx % HD_;
            int s = k0 + kk;
            float kv = 0.f, vv = 0.f;
            if (s < SEQ_) {
                size_t g = (((size_t)b * SEQ_ + s) * H_ + h) * HD_ + d;
                kv = K[g]; vv = V[g];
            }
            Ks[kk][d]  = kv;
            VsT[d][kk] = vv;
        }
        __syncthreads();

        // scores: thread -> q = lane, kk = warp*4 + j
        {
            const int q = lane;
#pragma unroll
            for (int j = 0; j < 4; j++) {
                int kk = warp * 4 + j;
                float s = 0.f;
#pragma unroll
                for (int d4 = 0; d4 < HD_; d4 += 4) {
                    float4 kv = *(const float4*)&Ks[kk][d4];
                    s += qreg[d4] * kv.x + qreg[d4 + 1] * kv.y
                       + qreg[d4 + 2] * kv.z + qreg[d4 + 3] * kv.w;
                }
                Ps[q][kk] = (k0 + kk < SEQ_) ? s * scale : -1e30f;
            }
        }
        __syncthreads();

        // online softmax, one row per lane of warp 0
        if (t < 32) {
            float m_old = m_sh[t];
            float mx = m_old;
#pragma unroll
            for (int kk = 0; kk < 32; kk++) mx = fmaxf(mx, Ps[t][kk]);
            float c = __expf(m_old - mx);
            float lsum = 0.f;
#pragma unroll
            for (int kk = 0; kk < 32; kk++) {
                float p = __expf(Ps[t][kk] - mx);
                Ps[t][kk] = p;
                lsum += p;
            }
            l_sh[t] = l_sh[t] * c + lsum;
            m_sh[t] = mx;
            corr_sh[t] = c;
        }
        __syncthreads();

        // PV accumulate: thread owns q = lane, d = dbase..dbase+10
        {
            const int q = lane;
            const float c = corr_sh[q];
#pragma unroll
            for (int i = 0; i < 11; i++) acc[i] *= c;
#pragma unroll
            for (int k4 = 0; k4 < 32; k4 += 4) {
                float4 p4 = *(const float4*)&Ps[q][k4];
#pragma unroll
                for (int i = 0; i < 11; i++) {
                    float4 v4 = *(const float4*)&VsT[dbase + i][k4];
                    acc[i] += p4.x * v4.x + p4.y * v4.y + p4.z * v4.z + p4.w * v4.w;
                }
            }
        }
        __syncthreads();
    }

    {
        const int q = lane;
        int s = q0 + q;
        if (s < SEQ_) {
            float inv = 1.f / l_sh[q];
#pragma unroll
            for (int i = 0; i < 11; i++) {
                O[(((size_t)b * SEQ_ + s) * H_ + h) * HD_ + dbase + i] = acc[i] * inv;
            }
        }
    }
}

// ---------------------------------------------------------------------------
extern "C" void kernel_launch(void* const* d_in, const int* in_sizes, int n_in,
                              void* d_out, int out_size)
{
    const float* X  = (const float*)d_in[0];
    const float* wq = (const float*)d_in[1];
    const float* bq = (const float*)d_in[2];
    const float* wk = (const float*)d_in[3];
    const float* bk = (const float*)d_in[4];
    const float* wv = (const float*)d_in[5];
    const float* bv = (const float*)d_in[6];
    const float* wo = (const float*)d_in[7];
    const float* bo = (const float*)d_in[8];
    float* out = (float*)d_out;

    float *Qp, *Kp, *Vp, *Cp;
    cudaGetSymbolAddress((void**)&Qp, g_Q);
    cudaGetSymbolAddress((void**)&Kp, g_K);
    cudaGetSymbolAddress((void**)&Vp, g_V);
    cudaGetSymbolAddress((void**)&Cp, g_C);

    dim3 ggrid(D_ / BN, (M_ + BM - 1) / BM);   // (11, 145)

    gemm_bias_kernel<<<ggrid, 256>>>(X, wq, bq, Qp, M_);
    gemm_bias_kernel<<<ggrid, 256>>>(X, wk, bk, Kp, M_);
    gemm_bias_kernel<<<ggrid, 256>>>(X, wv, bv, Vp, M_);

    rope_init_kernel<<<(SEQ_ * 44 + 255) / 256, 256>>>();
    const int rp = B_ * SEQ_ * H_ * 44;
    rope_apply_kernel<<<(rp + 255) / 256, 256>>>();

    dim3 agrid((SEQ_ + 31) / 32, H_, B_);      // (19, 16, 32)
    attn_kernel<<<agrid, 256>>>(Qp, Kp, Vp, Cp);

    gemm_bias_kernel<<<ggrid, 256>>>(Cp, wo, bo, out, M_);
}

// round 2
// speedup vs baseline: 1.5900x; 1.5900x over previous
#include <cuda_runtime.h>
#include <math.h>
#include <stdint.h>

// Problem constants
#define B_   32
#define SEQ_ 577
#define H_   16
#define HD_  88
#define D_   1408
#define IDX_ 24
#define M_   (B_ * SEQ_)   // 18464

// Scratch (device globals: no allocation allowed in kernel_launch)
__device__ float g_Q[(size_t)M_ * D_];
__device__ float g_K[(size_t)M_ * D_];
__device__ float g_V[(size_t)M_ * D_];
__device__ float g_C[(size_t)M_ * D_];
__device__ float g_cos[SEQ_ * 44];
__device__ float g_sin[SEQ_ * 44];

// ---------------------------------------------------------------------------
// TF32 helpers
// ---------------------------------------------------------------------------
__device__ __forceinline__ uint32_t f2tf32(float x) {
    uint32_t r;
    asm("cvt.rna.tf32.f32 %0, %1;" : "=r"(r) : "f"(x));
    return r;
}

__device__ __forceinline__ void mma_tf32(float* d, const uint32_t* a, const uint32_t* b) {
    asm volatile(
        "mma.sync.aligned.m16n8k8.row.col.f32.tf32.tf32.f32 "
        "{%0,%1,%2,%3},{%4,%5,%6,%7},{%8,%9},{%0,%1,%2,%3};"
        : "+f"(d[0]), "+f"(d[1]), "+f"(d[2]), "+f"(d[3])
        : "r"(a[0]), "r"(a[1]), "r"(a[2]), "r"(a[3]), "r"(b[0]), "r"(b[1]));
}

// ---------------------------------------------------------------------------
// GEMM: C[M][1408] = A[M][1408] @ W[1408][1408]^T + bias  (tf32 tensor cores)
// Block 128x128x16, 256 threads = 8 warps (4 Mrows x 2 Ncols), warp tile 32x64.
// SMEM: As[128][20], Bs[128][20] row-major padded (fragment LDS conflict-free),
// double buffered, tf32 rounding applied at staging.
// ---------------------------------------------------------------------------
constexpr int BM = 128, BN = 128, BK = 16;
constexpr int KPAD = 20;

__global__ __launch_bounds__(256) void gemm_tf32_kernel(
    const float* __restrict__ A, const float* __restrict__ W,
    const float* __restrict__ bias, float* __restrict__ C, int M)
{
    __shared__ __align__(16) float As[2][BM][KPAD];
    __shared__ __align__(16) float Bs[2][BN][KPAD];

    const int bm = blockIdx.y * BM;
    const int bn = blockIdx.x * BN;
    const int t  = threadIdx.x;
    const int lane = t & 31;
    const int warp = t >> 5;
    const int warpM = warp >> 1;        // 0..3 -> 32 rows each
    const int warpN = warp & 1;         // 0..1 -> 64 cols each
    const int g  = lane >> 2;           // 0..7
    const int tc = lane & 3;            // 0..3

    float acc[2][8][4];
#pragma unroll
    for (int mt = 0; mt < 2; mt++)
#pragma unroll
        for (int nt = 0; nt < 8; nt++)
#pragma unroll
            for (int i = 0; i < 4; i++) acc[mt][nt][i] = 0.f;

    // staging registers: 2 float4 from A, 2 from W
    float4 ar[2], br[2];

    auto ldg_tile = [&](int k0) {
#pragma unroll
        for (int i = 0; i < 2; i++) {
            int q   = t + 256 * i;       // 0..511
            int row = q >> 2;            // 0..127
            int kq  = q & 3;             // which float4 in BK
            int gm  = bm + row;
            if (gm < M)
                ar[i] = *(const float4*)&A[(size_t)gm * D_ + k0 + kq * 4];
            else
                ar[i] = make_float4(0.f, 0.f, 0.f, 0.f);
            br[i] = *(const float4*)&W[(size_t)(bn + row) * D_ + k0 + kq * 4];
        }
    };

    auto sts_tile = [&](int buf) {
#pragma unroll
        for (int i = 0; i < 2; i++) {
            int q   = t + 256 * i;
            int row = q >> 2;
            int kq  = q & 3;
            float4 av, bv;
            av.x = __uint_as_float(f2tf32(ar[i].x));
            av.y = __uint_as_float(f2tf32(ar[i].y));
            av.z = __uint_as_float(f2tf32(ar[i].z));
            av.w = __uint_as_float(f2tf32(ar[i].w));
            bv.x = __uint_as_float(f2tf32(br[i].x));
            bv.y = __uint_as_float(f2tf32(br[i].y));
            bv.z = __uint_as_float(f2tf32(br[i].z));
            bv.w = __uint_as_float(f2tf32(br[i].w));
            *(float4*)&As[buf][row][kq * 4] = av;
            *(float4*)&Bs[buf][row][kq * 4] = bv;
        }
    };

    const int NT = D_ / BK;   // 88

    ldg_tile(0);
    sts_tile(0);
    __syncthreads();

    for (int kt = 0; kt < NT; kt++) {
        const int cur = kt & 1;
        if (kt + 1 < NT) ldg_tile((kt + 1) * BK);

#pragma unroll
        for (int ks = 0; ks < 2; ks++) {
            const int kb = ks * 8;
            uint32_t af[2][4];
#pragma unroll
            for (int mt = 0; mt < 2; mt++) {
                int r = warpM * 32 + mt * 16;
                af[mt][0] = __float_as_uint(As[cur][r + g][kb + tc]);
                af[mt][1] = __float_as_uint(As[cur][r + g + 8][kb + tc]);
                af[mt][2] = __float_as_uint(As[cur][r + g][kb + tc + 4]);
                af[mt][3] = __float_as_uint(As[cur][r + g + 8][kb + tc + 4]);
            }
            uint32_t bf[8][2];
#pragma unroll
            for (int nt = 0; nt < 8; nt++) {
                int c = warpN * 64 + nt * 8;
                bf[nt][0] = __float_as_uint(Bs[cur][c + g][kb + tc]);
                bf[nt][1] = __float_as_uint(Bs[cur][c + g][kb + tc + 4]);
            }
#pragma unroll
            for (int mt = 0; mt < 2; mt++)
#pragma unroll
                for (int nt = 0; nt < 8; nt++)
                    mma_tf32(acc[mt][nt], af[mt], bf[nt]);
        }

        if (kt + 1 < NT) sts_tile(1 - cur);
        __syncthreads();
    }

    // epilogue: bias + store (float2 per c-pair)
    float bcol[8][2];
#pragma unroll
    for (int nt = 0; nt < 8; nt++) {
        int c = bn + warpN * 64 + nt * 8 + tc * 2;
        bcol[nt][0] = bias[c];
        bcol[nt][1] = bias[c + 1];
    }

#pragma unroll
    for (int mt = 0; mt < 2; mt++) {
        int row0 = bm + warpM * 32 + mt * 16 + g;
        int row1 = row0 + 8;
#pragma unroll
        for (int nt = 0; nt < 8; nt++) {
            int c = bn + warpN * 64 + nt * 8 + tc * 2;
            if (row0 < M) {
                float2 v = make_float2(acc[mt][nt][0] + bcol[nt][0],
                                       acc[mt][nt][1] + bcol[nt][1]);
                *(float2*)&C[(size_t)row0 * D_ + c] = v;
            }
            if (row1 < M) {
                float2 v = make_float2(acc[mt][nt][2] + bcol[nt][0],
                                       acc[mt][nt][3] + bcol[nt][1]);
                *(float2*)&C[(size_t)row1 * D_ + c] = v;
            }
        }
    }
}

// ---------------------------------------------------------------------------
// Rope tables: HF llama4 vision rope. freq_dim=44, rope_freq[i]=theta^{-2i/44}.
// ---------------------------------------------------------------------------
__global__ void rope_init_kernel()
{
    int idx = blockIdx.x * blockDim.x + threadIdx.x;
    if (idx >= SEQ_ * 44) return;
    int s = idx / 44, j = idx % 44;
    double f = 0.0;
    if (s != SEQ_ - 1) {
        int fx = s % IDX_, fy = s / IDX_;
        int i = (j < 22) ? j : j - 22;
        double rf = exp((-2.0 * (double)i / 44.0) * log(10000.0));
        double coord = (j < 22) ? (double)(fx + 1) : (double)(fy + 1);
        f = coord * rf;
    }
    g_cos[idx] = (float)cos(f);
    g_sin[idx] = (float)sin(f);
}

__global__ void rope_apply_kernel()
{
    int idx = blockIdx.x * blockDim.x + threadIdx.x;
    const int total = B_ * SEQ_ * H_ * 44;
    if (idx >= total) return;
    int j    = idx % 44;
    int rest = idx / 44;                 // (b*SEQ + s)*H + h
    int s    = (rest / H_) % SEQ_;
    size_t base = (size_t)rest * HD_ + 2 * j;
    float c  = g_cos[s * 44 + j];
    float sn = g_sin[s * 44 + j];

    float a = g_Q[base], b = g_Q[base + 1];
    g_Q[base]     = a * c - b * sn;
    g_Q[base + 1] = a * sn + b * c;
    a = g_K[base]; b = g_K[base + 1];
    g_K[base]     = a * c - b * sn;
    g_K[base + 1] = a * sn + b * c;
}

// ---------------------------------------------------------------------------
// Flash attention (fp32 SIMT) — unchanged from R0 baseline.
// ---------------------------------------------------------------------------
__global__ __launch_bounds__(256) void attn_kernel(
    const float* __restrict__ Q, const float* __restrict__ K,
    const float* __restrict__ V, float* __restrict__ O)
{
    const int qt = blockIdx.x, h = blockIdx.y, b = blockIdx.z;
    const int q0 = qt * 32;

    __shared__ __align__(16) float Qs[32][89];
    __shared__ __align__(16) float Ks[32][92];
    __shared__ __align__(16) float VsT[HD_][36];
    __shared__ __align__(16) float Ps[32][36];
    __shared__ float m_sh[32], l_sh[32], corr_sh[32];

    const int t    = threadIdx.x;
    const int lane = t & 31;
    const int warp = t >> 5;
    const int dbase = warp * 11;

    for (int idx = t; idx < 32 * HD_; idx += 256) {
        int qq = idx / HD_, d = idx % HD_;
        int s = q0 + qq;
        Qs[qq][d] = (s < SEQ_) ? Q[(((size_t)b * SEQ_ + s) * H_ + h) * HD_ + d] : 0.f;
    }
    if (t < 32) { m_sh[t] = -1e30f; l_sh[t] = 0.f; }
    __syncthreads();

    float qreg[HD_];
#pragma unroll
    for (int d = 0; d < HD_; d++) qreg[d] = Qs[lane][d];

    float acc[11];
#pragma unroll
    for (int i = 0; i < 11; i++) acc[i] = 0.f;

    const float scale = 0.10660035817780521f;

    for (int k0 = 0; k0 < SEQ_; k0 += 32) {
        for (int idx = t; idx < 32 * HD_; idx += 256) {
            int kk = idx / HD_, d = idx % HD_;
            int s = k0 + kk;
            float kv = 0.f, vv = 0.f;
            if (s < SEQ_) {
                size_t gg = (((size_t)b * SEQ_ + s) * H_ + h) * HD_ + d;
                kv = K[gg]; vv = V[gg];
            }
            Ks[kk][d]  = kv;
            VsT[d][kk] = vv;
        }
        __syncthreads();

        {
            const int q = lane;
#pragma unroll
            for (int j = 0; j < 4; j++) {
                int kk = warp * 4 + j;
                float s = 0.f;
#pragma unroll
                for (int d4 = 0; d4 < HD_; d4 += 4) {
                    float4 kv = *(const float4*)&Ks[kk][d4];
                    s += qreg[d4] * kv.x + qreg[d4 + 1] * kv.y
                       + qreg[d4 + 2] * kv.z + qreg[d4 + 3] * kv.w;
                }
                Ps[q][kk] = (k0 + kk < SEQ_) ? s * scale : -1e30f;
            }
        }
        __syncthreads();

        if (t < 32) {
            float m_old = m_sh[t];
            float mx = m_old;
#pragma unroll
            for (int kk = 0; kk < 32; kk++) mx = fmaxf(mx, Ps[t][kk]);
            float c = __expf(m_old - mx);
            float lsum = 0.f;
#pragma unroll
            for (int kk = 0; kk < 32; kk++) {
                float p = __expf(Ps[t][kk] - mx);
                Ps[t][kk] = p;
                lsum += p;
            }
            l_sh[t] = l_sh[t] * c + lsum;
            m_sh[t] = mx;
            corr_sh[t] = c;
        }
        __syncthreads();

        {
            const int q = lane;
            const float c = corr_sh[q];
#pragma unroll
            for (int i = 0; i < 11; i++) acc[i] *= c;
#pragma unroll
            for (int k4 = 0; k4 < 32; k4 += 4) {
                float4 p4 = *(const float4*)&Ps[q][k4];
#pragma unroll
                for (int i = 0; i < 11; i++) {
                    float4 v4 = *(const float4*)&VsT[dbase + i][k4];
                    acc[i] += p4.x * v4.x + p4.y * v4.y + p4.z * v4.z + p4.w * v4.w;
                }
            }
        }
        __syncthreads();
    }

    {
        const int q = lane;
        int s = q0 + q;
        if (s < SEQ_) {
            float inv = 1.f / l_sh[q];
#pragma unroll
            for (int i = 0; i < 11; i++) {
                O[(((size_t)b * SEQ_ + s) * H_ + h) * HD_ + dbase + i] = acc[i] * inv;
            }
        }
    }
}

// ---------------------------------------------------------------------------
extern "C" void kernel_launch(void* const* d_in, const int* in_sizes, int n_in,
                              void* d_out, int out_size)
{
    const float* X  = (const float*)d_in[0];
    const float* wq = (const float*)d_in[1];
    const float* bq = (const float*)d_in[2];
    const float* wk = (const float*)d_in[3];
    const float* bk = (const float*)d_in[4];
    const float* wv = (const float*)d_in[5];
    const float* bv = (const float*)d_in[6];
    const float* wo = (const float*)d_in[7];
    const float* bo = (const float*)d_in[8];
    float* out = (float*)d_out;

    float *Qp, *Kp, *Vp, *Cp;
    cudaGetSymbolAddress((void**)&Qp, g_Q);
    cudaGetSymbolAddress((void**)&Kp, g_K);
    cudaGetSymbolAddress((void**)&Vp, g_V);
    cudaGetSymbolAddress((void**)&Cp, g_C);

    dim3 ggrid(D_ / BN, (M_ + BM - 1) / BM);   // (11, 145)

    gemm_tf32_kernel<<<ggrid, 256>>>(X, wq, bq, Qp, M_);
    gemm_tf32_kernel<<<ggrid, 256>>>(X, wk, bk, Kp, M_);
    gemm_tf32_kernel<<<ggrid, 256>>>(X, wv, bv, Vp, M_);

    rope_init_kernel<<<(SEQ_ * 44 + 255) / 256, 256>>>();
    const int rp = B_ * SEQ_ * H_ * 44;
    rope_apply_kernel<<<(rp + 255) / 256, 256>>>();

    dim3 agrid((SEQ_ + 31) / 32, H_, B_);      // (19, 16, 32)
    attn_kernel<<<agrid, 256>>>(Qp, Kp, Vp, Cp);

    gemm_tf32_kernel<<<ggrid, 256>>>(Cp, wo, bo, out, M_);
}

// round 4
// speedup vs baseline: 1.7040x; 1.0717x over previous
#include <cuda_runtime.h>
#include <math.h>
#include <stdint.h>

// Problem constants
#define B_   32
#define SEQ_ 577
#define H_   16
#define HD_  88
#define D_   1408
#define IDX_ 24
#define M_   (B_ * SEQ_)   // 18464

// Scratch (device globals)
__device__ float g_Q[(size_t)M_ * D_];
__device__ float g_K[(size_t)M_ * D_];
__device__ float g_V[(size_t)M_ * D_];
__device__ float g_C[(size_t)M_ * D_];
__device__ float g_cos[SEQ_ * 44];
__device__ float g_sin[SEQ_ * 44];

// ---------------------------------------------------------------------------
// helpers
// ---------------------------------------------------------------------------
__device__ __forceinline__ uint32_t smem_u32(const void* p) {
    uint32_t a;
    asm("{ .reg .u64 t; cvta.to.shared.u64 t, %1; cvt.u32.u64 %0, t; }" : "=r"(a) : "l"(p));
    return a;
}
__device__ __forceinline__ uint32_t f2tf32(float x) {
    uint32_t r;
    asm("cvt.rna.tf32.f32 %0, %1;" : "=r"(r) : "f"(x));
    return r;
}
__device__ __forceinline__ void mma_tf32(float* d, const uint32_t* a, const uint32_t* b) {
    asm volatile(
        "mma.sync.aligned.m16n8k8.row.col.f32.tf32.tf32.f32 "
        "{%0,%1,%2,%3},{%4,%5,%6,%7},{%8,%9},{%0,%1,%2,%3};"
        : "+f"(d[0]), "+f"(d[1]), "+f"(d[2]), "+f"(d[3])
        : "r"(a[0]), "r"(a[1]), "r"(a[2]), "r"(a[3]), "r"(b[0]), "r"(b[1]));
}

#define CP_ASYNC(dst, src, sz) \
    asm volatile("cp.async.cg.shared.global [%0], [%1], 16, %2;" \
                 :: "r"(dst), "l"(src), "r"(sz) : "memory")
#define CP_COMMIT() asm volatile("cp.async.commit_group;" ::: "memory")
#define CP_WAIT1()  asm volatile("cp.async.wait_group 1;" ::: "memory")
#define CP_WAIT0()  asm volatile("cp.async.wait_group 0;" ::: "memory")

// ---------------------------------------------------------------------------
// GEMM: C[M][1408] = A[M][1408] @ W[1408][1408]^T + bias  (mma.sync tf32)
// CTA 128x128, BK=32, cp.async 2-stage pipeline, SW128 XOR-swizzled smem
// (128B rows). 8 warps as 2M x 4N, warp tile 64x32 (4 m-frags x 4 n-frags).
// ---------------------------------------------------------------------------
constexpr int BM = 128, BN = 128, BK = 32;
constexpr int NKT = D_ / BK;              // 44
constexpr int ABYTES = BM * BK * 4;       // 16384
constexpr int STG    = 2 * ABYTES;        // A+B per stage = 32768
constexpr int GSMEM  = 2 * STG;           // 65536

__global__ __launch_bounds__(256, 2) void gemm_tc_kernel(
    const float* __restrict__ A, const float* __restrict__ W,
    const float* __restrict__ bias, float* __restrict__ C, int M)
{
    extern __shared__ __align__(128) char sm[];
    const uint32_t sbase = smem_u32(sm);
    const int t = threadIdx.x, lane = t & 31, wid = t >> 5;
    const int g = lane >> 2, tc = lane & 3;
    const int warpM = wid & 1;     // 0..1 (64 rows each)
    const int warpN = wid >> 1;    // 0..3 (32 cols each)
    const int bm = blockIdx.y * BM;
    const int bn = blockIdx.x * BN;

    float acc[4][4][4];
#pragma unroll
    for (int mt = 0; mt < 4; mt++)
#pragma unroll
        for (int nt = 0; nt < 4; nt++)
#pragma unroll
            for (int i = 0; i < 4; i++) acc[mt][nt][i] = 0.f;

    auto issue = [&](int kt, int stage) {
        const int k0 = kt * BK;
        uint32_t dA = sbase + stage * STG;
        uint32_t dB = dA + ABYTES;
#pragma unroll
        for (int i = 0; i < 4; i++) {
            int idx = t + 256 * i;          // 0..1023
            int row = idx >> 3;             // 0..127
            int c4  = idx & 7;              // 16B chunk within 128B row
            uint32_t sw = ((uint32_t)row << 7) + ((uint32_t)(c4 ^ (row & 7)) << 4);
            int gm = bm + row;
            const float* srcA = A + (size_t)(gm < M ? gm : 0) * D_ + k0 + c4 * 4;
            CP_ASYNC(dA + sw, srcA, (gm < M) ? 16 : 0);
            const float* srcB = W + (size_t)(bn + row) * D_ + k0 + c4 * 4;
            CP_ASYNC(dB + sw, srcB, 16);
        }
        CP_COMMIT();
    };

    issue(0, 0);
    for (int kt = 0; kt < NKT; kt++) {
        const int buf = kt & 1;
        if (kt + 1 < NKT) { issue(kt + 1, buf ^ 1); CP_WAIT1(); }
        else              { CP_WAIT0(); }
        __syncthreads();

        const char* pA = sm + buf * STG;
        const char* pB = pA + ABYTES;

#pragma unroll
        for (int ks = 0; ks < 4; ks++) {
            const int kb  = ks * 8;
            const int ch0 = kb >> 2;                 // chunk of cols kb+tc
            const int swc0 = ((ch0) ^ g) << 4;       // row&7 == g for all frag rows
            const int swc1 = ((ch0 + 1) ^ g) << 4;

            uint32_t af[4][4];
#pragma unroll
            for (int mt = 0; mt < 4; mt++) {
                int r0 = warpM * 64 + mt * 16 + g;
                const char* q0 = pA + r0 * 128 + (tc << 2);
                const char* q1 = q0 + 8 * 128;
                af[mt][0] = f2tf32(*(const float*)(q0 + swc0));
                af[mt][1] = f2tf32(*(const float*)(q1 + swc0));
                af[mt][2] = f2tf32(*(const float*)(q0 + swc1));
                af[mt][3] = f2tf32(*(const float*)(q1 + swc1));
            }
            uint32_t bf[4][2];
#pragma unroll
            for (int nt = 0; nt < 4; nt++) {
                int c0 = warpN * 32 + nt * 8 + g;
                const char* q = pB + c0 * 128 + (tc << 2);
                bf[nt][0] = f2tf32(*(const float*)(q + swc0));
                bf[nt][1] = f2tf32(*(const float*)(q + swc1));
            }
#pragma unroll
            for (int mt = 0; mt < 4; mt++)
#pragma unroll
                for (int nt = 0; nt < 4; nt++)
                    mma_tf32(acc[mt][nt], af[mt], bf[nt]);
        }
        __syncthreads();
    }

    // epilogue: bias + float2 stores
#pragma unroll
    for (int nt = 0; nt < 4; nt++) {
        int c = bn + warpN * 32 + nt * 8 + tc * 2;
        float b0 = bias[c], b1 = bias[c + 1];
#pragma unroll
        for (int mt = 0; mt < 4; mt++) {
            int r0 = bm + warpM * 64 + mt * 16 + g;
            if (r0 < M) {
                float2 v = make_float2(acc[mt][nt][0] + b0, acc[mt][nt][1] + b1);
                *(float2*)&C[(size_t)r0 * D_ + c] = v;
            }
            if (r0 + 8 < M) {
                float2 v = make_float2(acc[mt][nt][2] + b0, acc[mt][nt][3] + b1);
                *(float2*)&C[(size_t)(r0 + 8) * D_ + c] = v;
            }
        }
    }
}

// ---------------------------------------------------------------------------
// Rope tables + apply
// ---------------------------------------------------------------------------
__global__ void rope_init_kernel()
{
    int idx = blockIdx.x * blockDim.x + threadIdx.x;
    if (idx >= SEQ_ * 44) return;
    int s = idx / 44, j = idx % 44;
    double f = 0.0;
    if (s != SEQ_ - 1) {
        int fx = s % IDX_, fy = s / IDX_;
        int i = (j < 22) ? j : j - 22;
        double rf = exp((-2.0 * (double)i / 44.0) * log(10000.0));
        double coord = (j < 22) ? (double)(fx + 1) : (double)(fy + 1);
        f = coord * rf;
    }
    g_cos[idx] = (float)cos(f);
    g_sin[idx] = (float)sin(f);
}

__global__ void rope_apply_kernel()
{
    int idx = blockIdx.x * blockDim.x + threadIdx.x;
    const int total = B_ * SEQ_ * H_ * 44;
    if (idx >= total) return;
    int j    = idx % 44;
    int rest = idx / 44;
    int s    = (rest / H_) % SEQ_;
    size_t base = (size_t)rest * HD_ + 2 * j;
    float c  = g_cos[s * 44 + j];
    float sn = g_sin[s * 44 + j];

    float a = g_Q[base], b = g_Q[base + 1];
    g_Q[base]     = a * c - b * sn;
    g_Q[base + 1] = a * sn + b * c;
    a = g_K[base]; b = g_K[base + 1];
    g_K[base]     = a * c - b * sn;
    g_K[base + 1] = a * sn + b * c;
}

// ---------------------------------------------------------------------------
// Flash attention (fp32 SIMT) — unchanged.
// ---------------------------------------------------------------------------
__global__ __launch_bounds__(256) void attn_kernel(
    const float* __restrict__ Q, const float* __restrict__ K,
    const float* __restrict__ V, float* __restrict__ O)
{
    const int qt = blockIdx.x, h = blockIdx.y, b = blockIdx.z;
    const int q0 = qt * 32;

    __shared__ __align__(16) float Qs[32][89];
    __shared__ __align__(16) float Ks[32][92];
    __shared__ __align__(16) float VsT[HD_][36];
    __shared__ __align__(16) float Ps[32][36];
    __shared__ float m_sh[32], l_sh[32], corr_sh[32];

    const int t    = threadIdx.x;
    const int lane = t & 31;
    const int warp = t >> 5;
    const int dbase = warp * 11;

    for (int idx = t; idx < 32 * HD_; idx += 256) {
        int qq = idx / HD_, d = idx % HD_;
        int s = q0 + qq;
        Qs[qq][d] = (s < SEQ_) ? Q[(((size_t)b * SEQ_ + s) * H_ + h) * HD_ + d] : 0.f;
    }
    if (t < 32) { m_sh[t] = -1e30f; l_sh[t] = 0.f; }
    __syncthreads();

    float qreg[HD_];
#pragma unroll
    for (int d = 0; d < HD_; d++) qreg[d] = Qs[lane][d];

    float acc[11];
#pragma unroll
    for (int i = 0; i < 11; i++) acc[i] = 0.f;

    const float scale = 0.10660035817780521f;

    for (int k0 = 0; k0 < SEQ_; k0 += 32) {
        for (int idx = t; idx < 32 * HD_; idx += 256) {
            int kk = idx / HD_, d = idx % HD_;
            int s = k0 + kk;
            float kv = 0.f, vv = 0.f;
            if (s < SEQ_) {
                size_t gg = (((size_t)b * SEQ_ + s) * H_ + h) * HD_ + d;
                kv = K[gg]; vv = V[gg];
            }
            Ks[kk][d]  = kv;
            VsT[d][kk] = vv;
        }
        __syncthreads();

        {
            const int q = lane;
#pragma unroll
            for (int j = 0; j < 4; j++) {
                int kk = warp * 4 + j;
                float s = 0.f;
#pragma unroll
                for (int d4 = 0; d4 < HD_; d4 += 4) {
                    float4 kv = *(const float4*)&Ks[kk][d4];
                    s += qreg[d4] * kv.x + qreg[d4 + 1] * kv.y
                       + qreg[d4 + 2] * kv.z + qreg[d4 + 3] * kv.w;
                }
                Ps[q][kk] = (k0 + kk < SEQ_) ? s * scale : -1e30f;
            }
        }
        __syncthreads();

        if (t < 32) {
            float m_old = m_sh[t];
            float mx = m_old;
#pragma unroll
            for (int kk = 0; kk < 32; kk++) mx = fmaxf(mx, Ps[t][kk]);
            float c = __expf(m_old - mx);
            float lsum = 0.f;
#pragma unroll
            for (int kk = 0; kk < 32; kk++) {
                float p = __expf(Ps[t][kk] - mx);
                Ps[t][kk] = p;
                lsum += p;
            }
            l_sh[t] = l_sh[t] * c + lsum;
            m_sh[t] = mx;
            corr_sh[t] = c;
        }
        __syncthreads();

        {
            const int q = lane;
            const float c = corr_sh[q];
#pragma unroll
            for (int i = 0; i < 11; i++) acc[i] *= c;
#pragma unroll
            for (int k4 = 0; k4 < 32; k4 += 4) {
                float4 p4 = *(const float4*)&Ps[q][k4];
#pragma unroll
                for (int i = 0; i < 11; i++) {
                    float4 v4 = *(const float4*)&VsT[dbase + i][k4];
                    acc[i] += p4.x * v4.x + p4.y * v4.y + p4.z * v4.z + p4.w * v4.w;
                }
            }
        }
        __syncthreads();
    }

    {
        const int q = lane;
        int s = q0 + q;
        if (s < SEQ_) {
            float inv = 1.f / l_sh[q];
#pragma unroll
            for (int i = 0; i < 11; i++) {
                O[(((size_t)b * SEQ_ + s) * H_ + h) * HD_ + dbase + i] = acc[i] * inv;
            }
        }
    }
}

// ---------------------------------------------------------------------------
extern "C" void kernel_launch(void* const* d_in, const int* in_sizes, int n_in,
                              void* d_out, int out_size)
{
    const float* X  = (const float*)d_in[0];
    const float* wq = (const float*)d_in[1];
    const float* bq = (const float*)d_in[2];
    const float* wk = (const float*)d_in[3];
    const float* bk = (const float*)d_in[4];
    const float* wv = (const float*)d_in[5];
    const float* bv = (const float*)d_in[6];
    const float* wo = (const float*)d_in[7];
    const float* bo = (const float*)d_in[8];
    float* out = (float*)d_out;

    float *Qp, *Kp, *Vp, *Cp;
    cudaGetSymbolAddress((void**)&Qp, g_Q);
    cudaGetSymbolAddress((void**)&Kp, g_K);
    cudaGetSymbolAddress((void**)&Vp, g_V);
    cudaGetSymbolAddress((void**)&Cp, g_C);

    cudaFuncSetAttribute(gemm_tc_kernel,
                         cudaFuncAttributeMaxDynamicSharedMemorySize, GSMEM);

    dim3 ggrid(D_ / BN, (M_ + BM - 1) / BM);   // (11, 145)

    gemm_tc_kernel<<<ggrid, 256, GSMEM>>>(X, wq, bq, Qp, M_);
    gemm_tc_kernel<<<ggrid, 256, GSMEM>>>(X, wk, bk, Kp, M_);
    gemm_tc_kernel<<<ggrid, 256, GSMEM>>>(X, wv, bv, Vp, M_);

    rope_init_kernel<<<(SEQ_ * 44 + 255) / 256, 256>>>();
    const int rp = B_ * SEQ_ * H_ * 44;
    rope_apply_kernel<<<(rp + 255) / 256, 256>>>();

    dim3 agrid((SEQ_ + 31) / 32, H_, B_);
    attn_kernel<<<agrid, 256>>>(Qp, Kp, Vp, Cp);

    gemm_tc_kernel<<<ggrid, 256, GSMEM>>>(Cp, wo, bo, out, M_);
}

// round 5
// speedup vs baseline: 1.7423x; 1.0225x over previous
#include <cuda_runtime.h>
#include <math.h>
#include <stdint.h>

// Problem constants
#define B_   32
#define SEQ_ 577
#define H_   16
#define HD_  88
#define D_   1408
#define IDX_ 24
#define M_   (B_ * SEQ_)   // 18464

// Scratch (device globals)
__device__ float g_Q[(size_t)M_ * D_];
__device__ float g_K[(size_t)M_ * D_];
__device__ float g_V[(size_t)M_ * D_];
__device__ float g_C[(size_t)M_ * D_];
__device__ float g_X[(size_t)M_ * D_];          // tf32-rounded activations
__device__ float g_W[4][(size_t)D_ * D_];       // tf32-rounded weights
__device__ float g_cos[SEQ_ * 44];
__device__ float g_sin[SEQ_ * 44];

// ---------------------------------------------------------------------------
// helpers
// ---------------------------------------------------------------------------
__device__ __forceinline__ uint32_t smem_u32(const void* p) {
    uint32_t a;
    asm("{ .reg .u64 t; cvta.to.shared.u64 t, %1; cvt.u32.u64 %0, t; }" : "=r"(a) : "l"(p));
    return a;
}
__device__ __forceinline__ float f2tf32f(float x) {
    uint32_t r;
    asm("cvt.rna.tf32.f32 %0, %1;" : "=r"(r) : "f"(x));
    return __uint_as_float(r);
}
__device__ __forceinline__ void mma_tf32(float* d, const uint32_t* a, const uint32_t* b) {
    asm volatile(
        "mma.sync.aligned.m16n8k8.row.col.f32.tf32.tf32.f32 "
        "{%0,%1,%2,%3},{%4,%5,%6,%7},{%8,%9},{%0,%1,%2,%3};"
        : "+f"(d[0]), "+f"(d[1]), "+f"(d[2]), "+f"(d[3])
        : "r"(a[0]), "r"(a[1]), "r"(a[2]), "r"(a[3]), "r"(b[0]), "r"(b[1]));
}

#define CP_ASYNC(dst, src, sz) \
    asm volatile("cp.async.cg.shared.global [%0], [%1], 16, %2;" \
                 :: "r"(dst), "l"(src), "r"(sz) : "memory")
#define CP_COMMIT() asm volatile("cp.async.commit_group;" ::: "memory")
#define CP_WAIT1()  asm volatile("cp.async.wait_group 1;" ::: "memory")
#define CP_WAIT0()  asm volatile("cp.async.wait_group 0;" ::: "memory")

// ---------------------------------------------------------------------------
// tf32 pre-rounding pass (bandwidth-bound)
// ---------------------------------------------------------------------------
__global__ void tf32_round_kernel(const float* __restrict__ in,
                                  float* __restrict__ out, int n4)
{
    int i = blockIdx.x * blockDim.x + threadIdx.x;
    if (i >= n4) return;
    float4 v = ((const float4*)in)[i];
    v.x = f2tf32f(v.x); v.y = f2tf32f(v.y);
    v.z = f2tf32f(v.z); v.w = f2tf32f(v.w);
    ((float4*)out)[i] = v;
}

// ---------------------------------------------------------------------------
// GEMM: C[M][1408] = A[M][1408] @ W[1408][1408]^T + bias  (mma.sync tf32)
// A and W are PRE-ROUNDED to tf32. CTA 128x128, BK=32, cp.async 2-stage,
// SW128 XOR-swizzled smem. 8 warps = 2M x 4N, warp tile 64x32.
// ---------------------------------------------------------------------------
constexpr int BM = 128, BN = 128, BK = 32;
constexpr int NKT = D_ / BK;              // 44
constexpr int ABYTES = BM * BK * 4;       // 16384
constexpr int STG    = 2 * ABYTES;        // 32768
constexpr int GSMEM  = 2 * STG;           // 65536

__global__ __launch_bounds__(256, 2) void gemm_tc_kernel(
    const float* __restrict__ A, const float* __restrict__ W,
    const float* __restrict__ bias, float* __restrict__ C, int M)
{
    extern __shared__ __align__(128) char sm[];
    const uint32_t sbase = smem_u32(sm);
    const int t = threadIdx.x, lane = t & 31, wid = t >> 5;
    const int g = lane >> 2, tc = lane & 3;
    const int warpM = wid & 1;
    const int warpN = wid >> 1;
    const int bm = blockIdx.y * BM;
    const int bn = blockIdx.x * BN;

    float acc[4][4][4];
#pragma unroll
    for (int mt = 0; mt < 4; mt++)
#pragma unroll
        for (int nt = 0; nt < 4; nt++)
#pragma unroll
            for (int i = 0; i < 4; i++) acc[mt][nt][i] = 0.f;

    auto issue = [&](int kt, int stage) {
        const int k0 = kt * BK;
        uint32_t dA = sbase + stage * STG;
        uint32_t dB = dA + ABYTES;
#pragma unroll
        for (int i = 0; i < 4; i++) {
            int idx = t + 256 * i;
            int row = idx >> 3;
            int c4  = idx & 7;
            uint32_t sw = ((uint32_t)row << 7) + ((uint32_t)(c4 ^ (row & 7)) << 4);
            int gm = bm + row;
            const float* srcA = A + (size_t)(gm < M ? gm : 0) * D_ + k0 + c4 * 4;
            CP_ASYNC(dA + sw, srcA, (gm < M) ? 16 : 0);
            const float* srcB = W + (size_t)(bn + row) * D_ + k0 + c4 * 4;
            CP_ASYNC(dB + sw, srcB, 16);
        }
        CP_COMMIT();
    };

    issue(0, 0);
    for (int kt = 0; kt < NKT; kt++) {
        const int buf = kt & 1;
        if (kt + 1 < NKT) { issue(kt + 1, buf ^ 1); CP_WAIT1(); }
        else              { CP_WAIT0(); }
        __syncthreads();

        const char* pA = sm + buf * STG;
        const char* pB = pA + ABYTES;

#pragma unroll
        for (int ks = 0; ks < 4; ks++) {
            const int kb  = ks * 8;
            const int ch0 = kb >> 2;
            const int swc0 = ((ch0) ^ g) << 4;
            const int swc1 = ((ch0 + 1) ^ g) << 4;

            uint32_t af[4][4];
#pragma unroll
            for (int mt = 0; mt < 4; mt++) {
                int r0 = warpM * 64 + mt * 16 + g;
                const char* q0 = pA + r0 * 128 + (tc << 2);
                const char* q1 = q0 + 8 * 128;
                af[mt][0] = *(const uint32_t*)(q0 + swc0);
                af[mt][1] = *(const uint32_t*)(q1 + swc0);
                af[mt][2] = *(const uint32_t*)(q0 + swc1);
                af[mt][3] = *(const uint32_t*)(q1 + swc1);
            }
            uint32_t bf[4][2];
#pragma unroll
            for (int nt = 0; nt < 4; nt++) {
                int c0 = warpN * 32 + nt * 8 + g;
                const char* q = pB + c0 * 128 + (tc << 2);
                bf[nt][0] = *(const uint32_t*)(q + swc0);
                bf[nt][1] = *(const uint32_t*)(q + swc1);
            }
#pragma unroll
            for (int mt = 0; mt < 4; mt++)
#pragma unroll
                for (int nt = 0; nt < 4; nt++)
                    mma_tf32(acc[mt][nt], af[mt], bf[nt]);
        }
        __syncthreads();
    }

#pragma unroll
    for (int nt = 0; nt < 4; nt++) {
        int c = bn + warpN * 32 + nt * 8 + tc * 2;
        float b0 = bias[c], b1 = bias[c + 1];
#pragma unroll
        for (int mt = 0; mt < 4; mt++) {
            int r0 = bm + warpM * 64 + mt * 16 + g;
            if (r0 < M) {
                float2 v = make_float2(acc[mt][nt][0] + b0, acc[mt][nt][1] + b1);
                *(float2*)&C[(size_t)r0 * D_ + c] = v;
            }
            if (r0 + 8 < M) {
                float2 v = make_float2(acc[mt][nt][2] + b0, acc[mt][nt][3] + b1);
                *(float2*)&C[(size_t)(r0 + 8) * D_ + c] = v;
            }
        }
    }
}

// ---------------------------------------------------------------------------
// Rope tables + apply
// ---------------------------------------------------------------------------
__global__ void rope_init_kernel()
{
    int idx = blockIdx.x * blockDim.x + threadIdx.x;
    if (idx >= SEQ_ * 44) return;
    int s = idx / 44, j = idx % 44;
    double f = 0.0;
    if (s != SEQ_ - 1) {
        int fx = s % IDX_, fy = s / IDX_;
        int i = (j < 22) ? j : j - 22;
        double rf = exp((-2.0 * (double)i / 44.0) * log(10000.0));
        double coord = (j < 22) ? (double)(fx + 1) : (double)(fy + 1);
        f = coord * rf;
    }
    g_cos[idx] = (float)cos(f);
    g_sin[idx] = (float)sin(f);
}

__global__ void rope_apply_kernel()
{
    int idx = blockIdx.x * blockDim.x + threadIdx.x;
    const int total = B_ * SEQ_ * H_ * 44;
    if (idx >= total) return;
    int j    = idx % 44;
    int rest = idx / 44;
    int s    = (rest / H_) % SEQ_;
    size_t base = (size_t)rest * HD_ + 2 * j;
    float c  = g_cos[s * 44 + j];
    float sn = g_sin[s * 44 + j];

    float a = g_Q[base], b = g_Q[base + 1];
    g_Q[base]     = a * c - b * sn;
    g_Q[base + 1] = a * sn + b * c;
    a = g_K[base]; b = g_K[base + 1];
    g_K[base]     = a * c - b * sn;
    g_K[base + 1] = a * sn + b * c;
}

// ---------------------------------------------------------------------------
// Flash attention (fp32 SIMT). Softmax now parallel across all 256 threads
// (8 threads per row, shfl_xor reductions within 8-lane groups).
// ---------------------------------------------------------------------------
__global__ __launch_bounds__(256) void attn_kernel(
    const float* __restrict__ Q, const float* __restrict__ K,
    const float* __restrict__ V, float* __restrict__ O)
{
    const int qt = blockIdx.x, h = blockIdx.y, b = blockIdx.z;
    const int q0 = qt * 32;

    __shared__ __align__(16) float Qs[32][89];
    __shared__ __align__(16) float Ks[32][92];
    __shared__ __align__(16) float VsT[HD_][36];
    __shared__ __align__(16) float Ps[32][36];
    __shared__ float m_sh[32], l_sh[32], corr_sh[32];

    const int t    = threadIdx.x;
    const int lane = t & 31;
    const int warp = t >> 5;
    const int dbase = warp * 11;
    const int srow = t >> 3;        // 0..31 (softmax row)
    const int ssub = t & 7;         // 0..7

    for (int idx = t; idx < 32 * HD_; idx += 256) {
        int qq = idx / HD_, d = idx % HD_;
        int s = q0 + qq;
        Qs[qq][d] = (s < SEQ_) ? Q[(((size_t)b * SEQ_ + s) * H_ + h) * HD_ + d] : 0.f;
    }
    if (t < 32) { m_sh[t] = -1e30f; l_sh[t] = 0.f; }
    __syncthreads();

    float qreg[HD_];
#pragma unroll
    for (int d = 0; d < HD_; d++) qreg[d] = Qs[lane][d];

    float acc[11];
#pragma unroll
    for (int i = 0; i < 11; i++) acc[i] = 0.f;

    const float scale = 0.10660035817780521f;

    for (int k0 = 0; k0 < SEQ_; k0 += 32) {
        for (int idx = t; idx < 32 * HD_; idx += 256) {
            int kk = idx / HD_, d = idx % HD_;
            int s = k0 + kk;
            float kv = 0.f, vv = 0.f;
            if (s < SEQ_) {
                size_t gg = (((size_t)b * SEQ_ + s) * H_ + h) * HD_ + d;
                kv = K[gg]; vv = V[gg];
            }
            Ks[kk][d]  = kv;
            VsT[d][kk] = vv;
        }
        __syncthreads();

        {
            const int q = lane;
#pragma unroll
            for (int j = 0; j < 4; j++) {
                int kk = warp * 4 + j;
                float s = 0.f;
#pragma unroll
                for (int d4 = 0; d4 < HD_; d4 += 4) {
                    float4 kv = *(const float4*)&Ks[kk][d4];
                    s += qreg[d4] * kv.x + qreg[d4 + 1] * kv.y
                       + qreg[d4 + 2] * kv.z + qreg[d4 + 3] * kv.w;
                }
                Ps[q][kk] = (k0 + kk < SEQ_) ? s * scale : -1e30f;
            }
        }
        __syncthreads();

        // online softmax: 8 threads per row, 4 cols each
        {
            float m_old = m_sh[srow];
            float4 pv = *(const float4*)&Ps[srow][ssub * 4];
            float mx = fmaxf(fmaxf(pv.x, pv.y), fmaxf(pv.z, pv.w));
#pragma unroll
            for (int off = 4; off >= 1; off >>= 1)
                mx = fmaxf(mx, __shfl_xor_sync(0xffffffffu, mx, off));
            mx = fmaxf(mx, m_old);
            pv.x = __expf(pv.x - mx); pv.y = __expf(pv.y - mx);
            pv.z = __expf(pv.z - mx); pv.w = __expf(pv.w - mx);
            *(float4*)&Ps[srow][ssub * 4] = pv;
            float lsum = pv.x + pv.y + pv.z + pv.w;
#pragma unroll
            for (int off = 4; off >= 1; off >>= 1)
                lsum += __shfl_xor_sync(0xffffffffu, lsum, off);
            if (ssub == 0) {
                float c = __expf(m_old - mx);
                l_sh[srow] = l_sh[srow] * c + lsum;
                m_sh[srow] = mx;
                corr_sh[srow] = c;
            }
        }
        __syncthreads();

        {
            const int q = lane;
            const float c = corr_sh[q];
#pragma unroll
            for (int i = 0; i < 11; i++) acc[i] *= c;
#pragma unroll
            for (int k4 = 0; k4 < 32; k4 += 4) {
                float4 p4 = *(const float4*)&Ps[q][k4];
#pragma unroll
                for (int i = 0; i < 11; i++) {
                    float4 v4 = *(const float4*)&VsT[dbase + i][k4];
                    acc[i] += p4.x * v4.x + p4.y * v4.y + p4.z * v4.z + p4.w * v4.w;
                }
            }
        }
        __syncthreads();
    }

    {
        const int q = lane;
        int s = q0 + q;
        if (s < SEQ_) {
            float inv = 1.f / l_sh[q];
#pragma unroll
            for (int i = 0; i < 11; i++) {
                O[(((size_t)b * SEQ_ + s) * H_ + h) * HD_ + dbase + i] = acc[i] * inv;
            }
        }
    }
}

// ---------------------------------------------------------------------------
extern "C" void kernel_launch(void* const* d_in, const int* in_sizes, int n_in,
                              void* d_out, int out_size)
{
    const float* X  = (const float*)d_in[0];
    const float* wq = (const float*)d_in[1];
    const float* bq = (const float*)d_in[2];
    const float* wk = (const float*)d_in[3];
    const float* bk = (const float*)d_in[4];
    const float* wv = (const float*)d_in[5];
    const float* bv = (const float*)d_in[6];
    const float* wo = (const float*)d_in[7];
    const float* bo = (const float*)d_in[8];
    float* out = (float*)d_out;

    float *Qp, *Kp, *Vp, *Cp, *Xp, *Wp;
    cudaGetSymbolAddress((void**)&Qp, g_Q);
    cudaGetSymbolAddress((void**)&Kp, g_K);
    cudaGetSymbolAddress((void**)&Vp, g_V);
    cudaGetSymbolAddress((void**)&Cp, g_C);
    cudaGetSymbolAddress((void**)&Xp, g_X);
    cudaGetSymbolAddress((void**)&Wp, g_W);

    cudaFuncSetAttribute(gemm_tc_kernel,
                         cudaFuncAttributeMaxDynamicSharedMemorySize, GSMEM);

    const int WN4 = D_ * D_ / 4;
    const int XN4 = M_ * D_ / 4;
    tf32_round_kernel<<<(XN4 + 255) / 256, 256>>>(X,  Xp, XN4);
    tf32_round_kernel<<<(WN4 + 255) / 256, 256>>>(wq, Wp + 0 * (size_t)D_ * D_, WN4);
    tf32_round_kernel<<<(WN4 + 255) / 256, 256>>>(wk, Wp + 1 * (size_t)D_ * D_, WN4);
    tf32_round_kernel<<<(WN4 + 255) / 256, 256>>>(wv, Wp + 2 * (size_t)D_ * D_, WN4);
    tf32_round_kernel<<<(WN4 + 255) / 256, 256>>>(wo, Wp + 3 * (size_t)D_ * D_, WN4);

    dim3 ggrid(D_ / BN, (M_ + BM - 1) / BM);   // (11, 145)

    gemm_tc_kernel<<<ggrid, 256, GSMEM>>>(Xp, Wp + 0 * (size_t)D_ * D_, bq, Qp, M_);
    gemm_tc_kernel<<<ggrid, 256, GSMEM>>>(Xp, Wp + 1 * (size_t)D_ * D_, bk, Kp, M_);
    gemm_tc_kernel<<<ggrid, 256, GSMEM>>>(Xp, Wp + 2 * (size_t)D_ * D_, bv, Vp, M_);

    rope_init_kernel<<<(SEQ_ * 44 + 255) / 256, 256>>>();
    const int rp = B_ * SEQ_ * H_ * 44;
    rope_apply_kernel<<<(rp + 255) / 256, 256>>>();

    dim3 agrid((SEQ_ + 31) / 32, H_, B_);
    attn_kernel<<<agrid, 256>>>(Qp, Kp, Vp, Cp);

    tf32_round_kernel<<<(XN4 + 255) / 256, 256>>>(Cp, Xp, XN4);
    gemm_tc_kernel<<<ggrid, 256, GSMEM>>>(Xp, Wp + 3 * (size_t)D_ * D_, bo, out, M_);
}